// round 7
// baseline (speedup 1.0000x reference)
#include <cuda_runtime.h>
#include <cuda_bf16.h>
#include <math.h>
#include <stdint.h>

// ---------------- problem constants ----------------
#define BB 8
#define TT 2048
#define DD 128
#define HH 4
#define HD 32
#define DH 64
#define NTOK (BB*TT)
#define SCALE 0.17677669529663687f
#define LOG2E 1.4426950408889634f
#define LAMBDA_INIT 0.8f
#define LN_EPS 1e-5f
#define BAND 64

// ---------------- scratch ----------------
__device__ float g_Q[BB*HH*TT*DH];
__device__ float g_K[BB*HH*TT*DH];
__device__ float g_V[BB*HH*TT*DH];
__device__ float g_O[NTOK * 256];

// ---------------- helpers ----------------
__device__ __forceinline__ uint32_t f2tf(float x){
    uint32_t r; asm("cvt.rna.tf32.f32 %0, %1;" : "=r"(r) : "f"(x)); return r;
}
__device__ __forceinline__ float tfr(float x){ return __uint_as_float(f2tf(x)); }

__device__ __forceinline__ void mma8(float4& d, const uint32_t* a, const uint32_t* b, const float4& c){
    asm volatile("mma.sync.aligned.m16n8k8.row.col.f32.tf32.tf32.f32 "
        "{%0,%1,%2,%3}, {%4,%5,%6,%7}, {%8,%9}, {%10,%11,%12,%13};"
        : "=f"(d.x),"=f"(d.y),"=f"(d.z),"=f"(d.w)
        : "r"(a[0]),"r"(a[1]),"r"(a[2]),"r"(a[3]),
          "r"(b[0]),"r"(b[1]),
          "f"(c.x),"f"(c.y),"f"(c.z),"f"(c.w));
}
__device__ __forceinline__ void cp16(float* smem, const float* gmem){
    uint32_t s = (uint32_t)__cvta_generic_to_shared(smem);
    asm volatile("cp.async.cg.shared.global [%0], [%1], 16;" :: "r"(s), "l"(gmem));
}
#define CP_COMMIT asm volatile("cp.async.commit_group;")
#define CP_WAIT0 asm volatile("cp.async.wait_group 0;")
#define CP_WAIT1 asm volatile("cp.async.wait_group 1;")

// ================= K1: fused LN + QKV GEMM tf32 (16384 x 768 x 128) =================
// block 256 thr; A = full 128x128 token tile, LN'd in-place in smem; B 2-stage cp.async.
#define QKV_SAS 132
#define QKV_SBT (32*136)
__global__ __launch_bounds__(256) void qkv_gemm(const float* __restrict__ tokens,
                                                const float* __restrict__ ln_w,
                                                const float* __restrict__ ln_b,
                                                const float* __restrict__ wq,
                                                const float* __restrict__ wk,
                                                const float* __restrict__ wv){
    extern __shared__ float dynsm[];
    float* sA = dynsm;                  // [128][132] full K
    float* sB = dynsm + 128*QKV_SAS;    // 2 stages [32][136]

    int brow = blockIdx.x, bc = blockIdx.y;
    int tid = threadIdx.x;
    int w = tid >> 5, lane = tid & 31, g = lane >> 2, q = lane & 3;
    int wm = w >> 2, wn = w & 3;
    const float* W = (bc < 2) ? wq : (bc < 4 ? wk : wv);
    int colbase = (bc & 1) * 128;

    // issue A (full tile) then B stage 0
    #pragma unroll
    for (int f = tid; f < 4096; f += 256){
        int r = f >> 5, c4 = f & 31;
        cp16(sA + r*QKV_SAS + c4*4, tokens + (size_t)(brow*128 + r)*DD + c4*4);
    }
    CP_COMMIT;
    #pragma unroll
    for (int f = tid; f < 1024; f += 256){
        int kr = f >> 5, c4 = f & 31;
        cp16(sB + kr*136 + c4*4, W + (size_t)kr*256 + colbase + c4*4);
    }
    CP_COMMIT;

    float4 acc[4][4];
    #pragma unroll
    for (int i = 0; i < 4; i++)
        #pragma unroll
        for (int j = 0; j < 4; j++) acc[i][j] = make_float4(0.f,0.f,0.f,0.f);

    CP_WAIT1;           // A complete (B0 may still be in flight)
    __syncthreads();

    // ---- in-place LN: 2 threads per row, 3 smem passes ----
    {
        int r = tid >> 1, h = tid & 1;
        float* row = sA + r*QKV_SAS + h*64;
        float s = 0.f;
        #pragma unroll
        for (int j = 0; j < 16; j++){
            float4 v = *(const float4*)(row + j*4);
            s += v.x + v.y + v.z + v.w;
        }
        s += __shfl_xor_sync(0xffffffffu, s, 1);
        float mu = s * (1.0f / DD);
        float sq = 0.f;
        #pragma unroll
        for (int j = 0; j < 16; j++){
            float4 v = *(const float4*)(row + j*4);
            float a0=v.x-mu, a1=v.y-mu, a2=v.z-mu, a3=v.w-mu;
            sq += a0*a0 + a1*a1 + a2*a2 + a3*a3;
        }
        sq += __shfl_xor_sync(0xffffffffu, sq, 1);
        float rstd = rsqrtf(sq * (1.0f / DD) + LN_EPS);
        const float4* wp = (const float4*)(ln_w + h*64);
        const float4* bp = (const float4*)(ln_b + h*64);
        #pragma unroll
        for (int j = 0; j < 16; j++){
            float4 v = *(const float4*)(row + j*4);
            float4 wv4 = wp[j], bv4 = bp[j];
            float4 o;
            o.x = tfr((v.x-mu)*rstd*wv4.x + bv4.x);
            o.y = tfr((v.y-mu)*rstd*wv4.y + bv4.y);
            o.z = tfr((v.z-mu)*rstd*wv4.z + bv4.z);
            o.w = tfr((v.w-mu)*rstd*wv4.w + bv4.w);
            *(float4*)(row + j*4) = o;
        }
    }
    __syncthreads();

    for (int kc = 0; kc < 4; kc++){
        if (kc + 1 < 4){
            float* dB = sB + ((kc+1)&1)*QKV_SBT;
            #pragma unroll
            for (int f = tid; f < 1024; f += 256){
                int kr = f >> 5, c4 = f & 31;
                cp16(dB + kr*136 + c4*4, W + (size_t)((kc+1)*32 + kr)*256 + colbase + c4*4);
            }
            CP_COMMIT;
            CP_WAIT1;
        } else {
            CP_WAIT0;
        }
        __syncthreads();
        const float* sBc = sB + (kc&1)*QKV_SBT;
        #pragma unroll
        for (int ks = 0; ks < 4; ks++){
            uint32_t a[4][4];
            int kk = kc*32 + ks*8 + q;
            int kl = ks*8 + q;
            #pragma unroll
            for (int mt = 0; mt < 4; mt++){
                int r = wm*64 + mt*16 + g;
                a[mt][0] = __float_as_uint(sA[r*QKV_SAS + kk]);
                a[mt][1] = __float_as_uint(sA[(r+8)*QKV_SAS + kk]);
                a[mt][2] = __float_as_uint(sA[r*QKV_SAS + kk + 4]);
                a[mt][3] = __float_as_uint(sA[(r+8)*QKV_SAS + kk + 4]);
            }
            #pragma unroll
            for (int nt = 0; nt < 4; nt++){
                uint32_t b[2];
                int n = wn*32 + nt*8 + g;
                b[0] = __float_as_uint(sBc[kl*136 + n]);
                b[1] = __float_as_uint(sBc[(kl+4)*136 + n]);
                #pragma unroll
                for (int mt = 0; mt < 4; mt++)
                    mma8(acc[mt][nt], a[mt], b, acc[mt][nt]);
            }
        }
        __syncthreads();
    }

    int mat = bc >> 1;
    float* dst = (mat == 0) ? g_Q : (mat == 1 ? g_K : g_V);
    #pragma unroll
    for (int mt = 0; mt < 4; mt++){
        int r0 = brow*128 + wm*64 + mt*16 + g;
        int r1 = r0 + 8;
        int b0_ = r0 >> 11, t0 = r0 & (TT-1);
        int b1_ = r1 >> 11, t1 = r1 & (TT-1);
        #pragma unroll
        for (int nt = 0; nt < 4; nt++){
            int col = colbase + wn*32 + nt*8 + 2*q;
            int head = col >> 6, dim = col & 63;
            float* p0 = dst + ((size_t)((b0_*HH + head)*TT + t0))*DH + dim;
            float* p1 = dst + ((size_t)((b1_*HH + head)*TT + t1))*DH + dim;
            *(float2*)p0 = make_float2(tfr(acc[mt][nt].x), tfr(acc[mt][nt].y));
            *(float2*)p1 = make_float2(tfr(acc[mt][nt].z), tfr(acc[mt][nt].w));
        }
    }
}

// ================= K2: banded dual-softmax flash attention, KTILE=64, exp2-domain =================
#define SKT (64*68)
#define SVT (64*72)
#define SPW (16*36)
__global__ __launch_bounds__(128) void attn_kernel(
        const float* __restrict__ lq1, const float* __restrict__ lk1,
        const float* __restrict__ lq2, const float* __restrict__ lk2,
        const float* __restrict__ sig_s_p, const float* __restrict__ sig_n_p,
        const float* __restrict__ hnw, const float* __restrict__ hnb){
    extern __shared__ float dynsm[];
    float* sQ = dynsm;              // [64][68]
    float* sK = dynsm + 64*68;      // 2 stages [64][68]
    float* sV = sK + 2*SKT;         // 2 stages [64][72]
    float* sPb = sV + 2*SVT;        // 4 warps x 2 branches x [16][36]

    int bh = blockIdx.y;
    int q0 = blockIdx.x * 64;
    int tid = threadIdx.x;
    int w = tid >> 5, lane = tid & 31, g = lane >> 2, q = lane & 3;
    float* sP1 = sPb + w*(2*SPW);
    float* sP2 = sP1 + SPW;

    const float* Qb = g_Q + (size_t)bh * TT * DH;
    const float* Kb = g_K + (size_t)bh * TT * DH;
    const float* Vb = g_V + (size_t)bh * TT * DH;

    int klo = q0 - BAND; if (klo < 0) klo = 0;
    int khi = q0 + 64 + BAND; if (khi > TT) khi = TT;
    int ntile = (khi - klo) >> 6;

    #pragma unroll
    for (int f = tid; f < 1024; f += 128){
        int r = f >> 4, c4 = f & 15;
        cp16(sQ + r*68 + c4*4, Qb + (size_t)(q0 + r)*DH + c4*4);
    }
    CP_COMMIT;
    #pragma unroll
    for (int f = tid; f < 1024; f += 128){
        int kk = f >> 4, c4 = f & 15;
        cp16(sK + kk*68 + c4*4, Kb + (size_t)(klo + kk)*DH + c4*4);
        cp16(sV + kk*72 + c4*4, Vb + (size_t)(klo + kk)*DH + c4*4);
    }
    CP_COMMIT;

    float e1 = 0.f, e2 = 0.f;
    #pragma unroll
    for (int i = 0; i < HD; i++){ e1 += lq1[i]*lk1[i]; e2 += lq2[i]*lk2[i]; }
    float lam = __expf(e1) - __expf(e2) + LAMBDA_INIT;
    float sig_s = fmaxf(sig_s_p[0], 1.0f), sig_n = fmaxf(sig_n_p[0], 1.0f);
    float sc2 = SCALE * LOG2E;
    float c1 = -0.5f * LOG2E / (sig_s * sig_s), c2 = -0.5f * LOG2E / (sig_n * sig_n);

    CP_WAIT1;
    __syncthreads();

    uint32_t qa1[4][4], qa2[4][4];
    {
        int rb = (w*16 + g)*68;
        #pragma unroll
        for (int ks = 0; ks < 4; ks++){
            int d0 = ks*8 + q;
            qa1[ks][0] = __float_as_uint(sQ[rb + d0]);
            qa1[ks][1] = __float_as_uint(sQ[rb + 8*68 + d0]);
            qa1[ks][2] = __float_as_uint(sQ[rb + d0 + 4]);
            qa1[ks][3] = __float_as_uint(sQ[rb + 8*68 + d0 + 4]);
            qa2[ks][0] = __float_as_uint(sQ[rb + d0 + 32]);
            qa2[ks][1] = __float_as_uint(sQ[rb + 8*68 + d0 + 32]);
            qa2[ks][2] = __float_as_uint(sQ[rb + d0 + 36]);
            qa2[ks][3] = __float_as_uint(sQ[rb + 8*68 + d0 + 36]);
        }
    }

    float4 o1[8], o2[8];
    #pragma unroll
    for (int nt = 0; nt < 8; nt++){
        o1[nt] = make_float4(0.f,0.f,0.f,0.f);
        o2[nt] = make_float4(0.f,0.f,0.f,0.f);
    }
    float m1lo = -1e30f, m1hi = -1e30f, m2lo = -1e30f, m2hi = -1e30f;
    float l1lo = 0.f, l1hi = 0.f, l2lo = 0.f, l2hi = 0.f;

    float row_lo = (float)(q0 + w*16 + g);
    float row_hi = row_lo + 8.0f;

    for (int it = 0; it < ntile; it++){
        int ksb = klo + it*64;
        if (it + 1 < ntile){
            float* dK = sK + ((it+1)&1)*SKT;
            float* dV = sV + ((it+1)&1)*SVT;
            int kn = klo + (it+1)*64;
            #pragma unroll
            for (int f = tid; f < 1024; f += 128){
                int kk = f >> 4, c4 = f & 15;
                cp16(dK + kk*68 + c4*4, Kb + (size_t)(kn + kk)*DH + c4*4);
                cp16(dV + kk*72 + c4*4, Vb + (size_t)(kn + kk)*DH + c4*4);
            }
            CP_COMMIT;
            CP_WAIT1;
        } else {
            CP_WAIT0;
        }
        __syncthreads();
        const float* sKc = sK + (it&1)*SKT;
        const float* sVc = sV + (it&1)*SVT;

        // ---- scores over 64 keys, both branches ----
        float4 s1[8], s2[8];
        #pragma unroll
        for (int nt = 0; nt < 8; nt++){ s1[nt] = make_float4(0.f,0.f,0.f,0.f); s2[nt] = s1[nt]; }
        #pragma unroll
        for (int ks = 0; ks < 4; ks++){
            int d0 = ks*8 + q;
            #pragma unroll
            for (int nt = 0; nt < 8; nt++){
                uint32_t b1[2], b2[2];
                int kb = (nt*8 + g)*68 + d0;
                b1[0] = __float_as_uint(sKc[kb]);
                b1[1] = __float_as_uint(sKc[kb + 4]);
                b2[0] = __float_as_uint(sKc[kb + 32]);
                b2[1] = __float_as_uint(sKc[kb + 36]);
                mma8(s1[nt], qa1[ks], b1, s1[nt]);
                mma8(s2[nt], qa2[ks], b2, s2[nt]);
            }
        }

        // ---- bias (log2 domain) + one online update per 64 keys ----
        float rm1lo = -1e30f, rm1hi = -1e30f, rm2lo = -1e30f, rm2hi = -1e30f;
        #pragma unroll
        for (int nt = 0; nt < 8; nt++){
            float k0f = (float)(ksb + nt*8 + 2*q);
            float rx_lo = k0f - row_lo,   ry_lo = k0f + 1.0f - row_lo;
            float rx_hi = k0f - row_hi,   ry_hi = k0f + 1.0f - row_hi;
            s1[nt].x = s1[nt].x*sc2 + rx_lo*rx_lo*c1;
            s1[nt].y = s1[nt].y*sc2 + ry_lo*ry_lo*c1;
            s1[nt].z = s1[nt].z*sc2 + rx_hi*rx_hi*c1;
            s1[nt].w = s1[nt].w*sc2 + ry_hi*ry_hi*c1;
            s2[nt].x = s2[nt].x*sc2 + rx_lo*rx_lo*c2;
            s2[nt].y = s2[nt].y*sc2 + ry_lo*ry_lo*c2;
            s2[nt].z = s2[nt].z*sc2 + rx_hi*rx_hi*c2;
            s2[nt].w = s2[nt].w*sc2 + ry_hi*ry_hi*c2;
            rm1lo = fmaxf(rm1lo, fmaxf(s1[nt].x, s1[nt].y));
            rm1hi = fmaxf(rm1hi, fmaxf(s1[nt].z, s1[nt].w));
            rm2lo = fmaxf(rm2lo, fmaxf(s2[nt].x, s2[nt].y));
            rm2hi = fmaxf(rm2hi, fmaxf(s2[nt].z, s2[nt].w));
        }
        #pragma unroll
        for (int o = 1; o <= 2; o <<= 1){
            rm1lo = fmaxf(rm1lo, __shfl_xor_sync(0xffffffffu, rm1lo, o));
            rm1hi = fmaxf(rm1hi, __shfl_xor_sync(0xffffffffu, rm1hi, o));
            rm2lo = fmaxf(rm2lo, __shfl_xor_sync(0xffffffffu, rm2lo, o));
            rm2hi = fmaxf(rm2hi, __shfl_xor_sync(0xffffffffu, rm2hi, o));
        }
        float mn1lo = fmaxf(m1lo, rm1lo), mn1hi = fmaxf(m1hi, rm1hi);
        float mn2lo = fmaxf(m2lo, rm2lo), mn2hi = fmaxf(m2hi, rm2hi);
        float f1lo = exp2f(m1lo - mn1lo), f1hi = exp2f(m1hi - mn1hi);
        float f2lo = exp2f(m2lo - mn2lo), f2hi = exp2f(m2hi - mn2hi);
        m1lo = mn1lo; m1hi = mn1hi; m2lo = mn2lo; m2hi = mn2hi;
        #pragma unroll
        for (int nt = 0; nt < 8; nt++){
            o1[nt].x *= f1lo; o1[nt].y *= f1lo; o1[nt].z *= f1hi; o1[nt].w *= f1hi;
            o2[nt].x *= f2lo; o2[nt].y *= f2lo; o2[nt].z *= f2hi; o2[nt].w *= f2hi;
        }

        float rs1lo = 0.f, rs1hi = 0.f, rs2lo = 0.f, rs2hi = 0.f;
        #pragma unroll
        for (int half = 0; half < 2; half++){
            #pragma unroll
            for (int nth = 0; nth < 4; nth++){
                int nt = half*4 + nth;
                float ax = exp2f(s1[nt].x - mn1lo), ay = exp2f(s1[nt].y - mn1lo);
                float az = exp2f(s1[nt].z - mn1hi), aw = exp2f(s1[nt].w - mn1hi);
                rs1lo += ax + ay;  rs1hi += az + aw;
                *(float2*)(sP1 + g*36 + nth*8 + 2*q)     = make_float2(ax, ay);
                *(float2*)(sP1 + (g+8)*36 + nth*8 + 2*q) = make_float2(az, aw);
                float bx = exp2f(s2[nt].x - mn2lo), by = exp2f(s2[nt].y - mn2lo);
                float bz = exp2f(s2[nt].z - mn2hi), bw = exp2f(s2[nt].w - mn2hi);
                rs2lo += bx + by;  rs2hi += bz + bw;
                *(float2*)(sP2 + g*36 + nth*8 + 2*q)     = make_float2(bx, by);
                *(float2*)(sP2 + (g+8)*36 + nth*8 + 2*q) = make_float2(bz, bw);
            }
            __syncwarp();
            #pragma unroll
            for (int ks = 0; ks < 4; ks++){
                uint32_t a1[4], a2[4];
                int pk = ks*8 + q;
                a1[0] = __float_as_uint(sP1[g*36 + pk]);
                a1[1] = __float_as_uint(sP1[(g+8)*36 + pk]);
                a1[2] = __float_as_uint(sP1[g*36 + pk + 4]);
                a1[3] = __float_as_uint(sP1[(g+8)*36 + pk + 4]);
                a2[0] = __float_as_uint(sP2[g*36 + pk]);
                a2[1] = __float_as_uint(sP2[(g+8)*36 + pk]);
                a2[2] = __float_as_uint(sP2[g*36 + pk + 4]);
                a2[3] = __float_as_uint(sP2[(g+8)*36 + pk + 4]);
                int kv = half*32 + ks*8 + q;
                #pragma unroll
                for (int nt = 0; nt < 8; nt++){
                    uint32_t b[2];
                    b[0] = __float_as_uint(sVc[kv*72 + nt*8 + g]);
                    b[1] = __float_as_uint(sVc[(kv+4)*72 + nt*8 + g]);
                    mma8(o1[nt], a1, b, o1[nt]);
                    mma8(o2[nt], a2, b, o2[nt]);
                }
            }
            __syncwarp();
        }
        #pragma unroll
        for (int o = 1; o <= 2; o <<= 1){
            rs1lo += __shfl_xor_sync(0xffffffffu, rs1lo, o);
            rs1hi += __shfl_xor_sync(0xffffffffu, rs1hi, o);
            rs2lo += __shfl_xor_sync(0xffffffffu, rs2lo, o);
            rs2hi += __shfl_xor_sync(0xffffffffu, rs2hi, o);
        }
        l1lo = l1lo*f1lo + rs1lo;  l1hi = l1hi*f1hi + rs1hi;
        l2lo = l2lo*f2lo + rs2lo;  l2hi = l2hi*f2hi + rs2hi;
        __syncthreads();
    }

    // ---- epilogue ----
    float inv1lo = 1.0f / l1lo, inv1hi = 1.0f / l1hi;
    float inv2lo = lam / l2lo,  inv2hi = lam / l2hi;
    float4 ov[8];
    float slo = 0.f, shi = 0.f;
    #pragma unroll
    for (int nt = 0; nt < 8; nt++){
        ov[nt].x = o1[nt].x*inv1lo - o2[nt].x*inv2lo;
        ov[nt].y = o1[nt].y*inv1lo - o2[nt].y*inv2lo;
        ov[nt].z = o1[nt].z*inv1hi - o2[nt].z*inv2hi;
        ov[nt].w = o1[nt].w*inv1hi - o2[nt].w*inv2hi;
        slo += ov[nt].x + ov[nt].y;
        shi += ov[nt].z + ov[nt].w;
    }
    #pragma unroll
    for (int o = 1; o <= 2; o <<= 1){
        slo += __shfl_xor_sync(0xffffffffu, slo, o);
        shi += __shfl_xor_sync(0xffffffffu, shi, o);
    }
    float mulo = slo * (1.0f / DH), muhi = shi * (1.0f / DH);
    float vlo = 0.f, vhi = 0.f;
    #pragma unroll
    for (int nt = 0; nt < 8; nt++){
        float a0 = ov[nt].x - mulo, a1 = ov[nt].y - mulo;
        float a2 = ov[nt].z - muhi, a3 = ov[nt].w - muhi;
        vlo += a0*a0 + a1*a1;  vhi += a2*a2 + a3*a3;
    }
    #pragma unroll
    for (int o = 1; o <= 2; o <<= 1){
        vlo += __shfl_xor_sync(0xffffffffu, vlo, o);
        vhi += __shfl_xor_sync(0xffffffffu, vhi, o);
    }
    float rslo = rsqrtf(vlo * (1.0f / DH) + LN_EPS);
    float rshi = rsqrtf(vhi * (1.0f / DH) + LN_EPS);

    int b_ = bh >> 2, h = bh & 3;
    int tok_lo = b_*TT + q0 + w*16 + g;
    float* OdLo = g_O + (size_t)tok_lo*256 + h*DH;
    float* OdHi = OdLo + 8*256;
    #pragma unroll
    for (int nt = 0; nt < 8; nt++){
        float2 wv2 = *(const float2*)(hnw + nt*8 + 2*q);
        float2 bv2 = *(const float2*)(hnb + nt*8 + 2*q);
        float y0 = ((ov[nt].x - mulo)*rslo*wv2.x + bv2.x) * (1.0f - LAMBDA_INIT);
        float y1 = ((ov[nt].y - mulo)*rslo*wv2.y + bv2.y) * (1.0f - LAMBDA_INIT);
        float y2 = ((ov[nt].z - muhi)*rshi*wv2.x + bv2.x) * (1.0f - LAMBDA_INIT);
        float y3 = ((ov[nt].w - muhi)*rshi*wv2.y + bv2.y) * (1.0f - LAMBDA_INIT);
        *(float2*)(OdLo + nt*8 + 2*q) = make_float2(y0, y1);
        *(float2*)(OdHi + nt*8 + 2*q) = make_float2(y2, y3);
    }
}

// ================= K3: output GEMM tf32 (16384 x 128 x 256) + residual =================
// 64x128 tile, 256 threads (8 warps, each 32x32), 2-stage cp.async.
#define OUT_SAT (64*36)
#define OUT_SBT (32*136)
__global__ __launch_bounds__(256) void out_gemm(const float* __restrict__ wo,
                                                const float* __restrict__ tokens,
                                                float* __restrict__ out){
    extern __shared__ float dynsm[];
    float* sA = dynsm;                 // 2 stages [64][36]
    float* sB = dynsm + 2*OUT_SAT;     // 2 stages [32][136]

    int brow = blockIdx.x;             // 0..255
    int tid = threadIdx.x;
    int w = tid >> 5, lane = tid & 31, g = lane >> 2, q = lane & 3;
    int wm = w >> 2, wn = w & 3;       // 2 x 4 warps over 64 x 128
    float4 acc[2][4];
    #pragma unroll
    for (int i = 0; i < 2; i++)
        #pragma unroll
        for (int j = 0; j < 4; j++) acc[i][j] = make_float4(0.f,0.f,0.f,0.f);

    #pragma unroll
    for (int f = tid; f < 512; f += 256){
        int r = f >> 3, c4 = f & 7;
        cp16(sA + r*36 + c4*4, g_O + (size_t)(brow*64 + r)*256 + c4*4);
    }
    #pragma unroll
    for (int f = tid; f < 1024; f += 256){
        int kr = f >> 5, c4 = f & 31;
        cp16(sB + kr*136 + c4*4, wo + (size_t)kr*DD + c4*4);
    }
    CP_COMMIT;

    for (int kc = 0; kc < 8; kc++){
        if (kc + 1 < 8){
            float* dA = sA + ((kc+1)&1)*OUT_SAT;
            float* dB = sB + ((kc+1)&1)*OUT_SBT;
            #pragma unroll
            for (int f = tid; f < 512; f += 256){
                int r = f >> 3, c4 = f & 7;
                cp16(dA + r*36 + c4*4, g_O + (size_t)(brow*64 + r)*256 + (kc+1)*32 + c4*4);
            }
            #pragma unroll
            for (int f = tid; f < 1024; f += 256){
                int kr = f >> 5, c4 = f & 31;
                cp16(dB + kr*136 + c4*4, wo + (size_t)((kc+1)*32 + kr)*DD + c4*4);
            }
            CP_COMMIT;
            CP_WAIT1;
        } else {
            CP_WAIT0;
        }
        __syncthreads();
        const float* sAc = sA + (kc&1)*OUT_SAT;
        const float* sBc = sB + (kc&1)*OUT_SBT;
        #pragma unroll
        for (int ks = 0; ks < 4; ks++){
            uint32_t a[2][4];
            int kk = ks*8 + q;
            #pragma unroll
            for (int mt = 0; mt < 2; mt++){
                int r = wm*32 + mt*16 + g;
                a[mt][0] = __float_as_uint(sAc[r*36 + kk]);
                a[mt][1] = __float_as_uint(sAc[(r+8)*36 + kk]);
                a[mt][2] = __float_as_uint(sAc[r*36 + kk + 4]);
                a[mt][3] = __float_as_uint(sAc[(r+8)*36 + kk + 4]);
            }
            #pragma unroll
            for (int nt = 0; nt < 4; nt++){
                uint32_t b[2];
                int n = wn*32 + nt*8 + g;
                b[0] = __float_as_uint(sBc[kk*136 + n]);
                b[1] = __float_as_uint(sBc[(kk+4)*136 + n]);
                #pragma unroll
                for (int mt = 0; mt < 2; mt++)
                    mma8(acc[mt][nt], a[mt], b, acc[mt][nt]);
            }
        }
        __syncthreads();
    }

    #pragma unroll
    for (int mt = 0; mt < 2; mt++){
        int r0 = brow*64 + wm*32 + mt*16 + g;
        int r1 = r0 + 8;
        #pragma unroll
        for (int nt = 0; nt < 4; nt++){
            int col = wn*32 + nt*8 + 2*q;
            float2 t0 = *(const float2*)(tokens + (size_t)r0*DD + col);
            float2 t1 = *(const float2*)(tokens + (size_t)r1*DD + col);
            *(float2*)(out + (size_t)r0*DD + col) = make_float2(acc[mt][nt].x + t0.x, acc[mt][nt].y + t0.y);
            *(float2*)(out + (size_t)r1*DD + col) = make_float2(acc[mt][nt].z + t1.x, acc[mt][nt].w + t1.y);
        }
    }
}

// ================= launch =================
#define QKV_SMEM ((128*QKV_SAS + 2*QKV_SBT) * 4)
#define ATTN_SMEM ((64*68 + 2*SKT + 2*SVT + 4*2*SPW) * 4)
#define OUT_SMEM ((2*OUT_SAT + 2*OUT_SBT) * 4)

extern "C" void kernel_launch(void* const* d_in, const int* in_sizes, int n_in,
                              void* d_out, int out_size){
    const float* tokens = (const float*)d_in[0];
    const float* ln_w   = (const float*)d_in[1];
    const float* ln_b   = (const float*)d_in[2];
    const float* wq     = (const float*)d_in[3];
    const float* wk     = (const float*)d_in[4];
    const float* wv     = (const float*)d_in[5];
    const float* wo     = (const float*)d_in[6];
    const float* lq1    = (const float*)d_in[7];
    const float* lk1    = (const float*)d_in[8];
    const float* lq2    = (const float*)d_in[9];
    const float* lk2    = (const float*)d_in[10];
    const float* sig_s  = (const float*)d_in[11];
    const float* sig_n  = (const float*)d_in[12];
    const float* hnw    = (const float*)d_in[13];
    const float* hnb    = (const float*)d_in[14];
    float* out = (float*)d_out;

    static int attr_done = 0;
    if (!attr_done){
        cudaFuncSetAttribute(qkv_gemm, cudaFuncAttributeMaxDynamicSharedMemorySize, QKV_SMEM);
        cudaFuncSetAttribute(attn_kernel, cudaFuncAttributeMaxDynamicSharedMemorySize, ATTN_SMEM);
        cudaFuncSetAttribute(out_gemm, cudaFuncAttributeMaxDynamicSharedMemorySize, OUT_SMEM);
        attr_done = 1;
    }

    qkv_gemm<<<dim3(NTOK/128, 6), 256, QKV_SMEM>>>(tokens, ln_w, ln_b, wq, wk, wv);
    attn_kernel<<<dim3(TT/64, BB*HH), 128, ATTN_SMEM>>>(lq1, lk1, lq2, lk2, sig_s, sig_n, hnw, hnb);
    out_gemm<<<NTOK/64, 256, OUT_SMEM>>>(wo, tokens, out);
}

// round 9
// speedup vs baseline: 1.0620x; 1.0620x over previous
#include <cuda_runtime.h>
#include <cuda_bf16.h>
#include <math.h>
#include <stdint.h>

// ---------------- problem constants ----------------
#define BB 8
#define TT 2048
#define DD 128
#define HH 4
#define HD 32
#define DH 64
#define NTOK (BB*TT)
#define SCALE 0.17677669529663687f
#define LOG2E 1.4426950408889634f
#define LAMBDA_INIT 0.8f
#define LN_EPS 1e-5f
#define BAND 64

// ---------------- scratch ----------------
__device__ float g_xnorm[NTOK * DD];
__device__ float g_Q[BB*HH*TT*DH];
__device__ float g_K[BB*HH*TT*DH];
__device__ float g_V[BB*HH*TT*DH];
__device__ float g_O[NTOK * 256];

// ---------------- helpers ----------------
__device__ __forceinline__ uint32_t f2tf(float x){
    uint32_t r; asm("cvt.rna.tf32.f32 %0, %1;" : "=r"(r) : "f"(x)); return r;
}
__device__ __forceinline__ float tfr(float x){ return __uint_as_float(f2tf(x)); }

__device__ __forceinline__ void mma8(float4& d, const uint32_t* a, const uint32_t* b, const float4& c){
    asm volatile("mma.sync.aligned.m16n8k8.row.col.f32.tf32.tf32.f32 "
        "{%0,%1,%2,%3}, {%4,%5,%6,%7}, {%8,%9}, {%10,%11,%12,%13};"
        : "=f"(d.x),"=f"(d.y),"=f"(d.z),"=f"(d.w)
        : "r"(a[0]),"r"(a[1]),"r"(a[2]),"r"(a[3]),
          "r"(b[0]),"r"(b[1]),
          "f"(c.x),"f"(c.y),"f"(c.z),"f"(c.w));
}
__device__ __forceinline__ void cp16(float* smem, const float* gmem){
    uint32_t s = (uint32_t)__cvta_generic_to_shared(smem);
    asm volatile("cp.async.cg.shared.global [%0], [%1], 16;" :: "r"(s), "l"(gmem));
}
#define CP_COMMIT asm volatile("cp.async.commit_group;")
#define CP_WAIT0 asm volatile("cp.async.wait_group 0;")
#define CP_WAIT1 asm volatile("cp.async.wait_group 1;")

// ================= K0: layernorm (tf32-rounded output) =================
__global__ __launch_bounds__(256) void ln_kernel(const float* __restrict__ x,
                                                 const float* __restrict__ w,
                                                 const float* __restrict__ b){
    int token = blockIdx.x * 8 + threadIdx.y;
    int lane  = threadIdx.x;
    const float4* xr = (const float4*)(x + (size_t)token * DD);
    float4 v = xr[lane];
    float s = v.x + v.y + v.z + v.w;
    #pragma unroll
    for (int o = 16; o; o >>= 1) s += __shfl_xor_sync(0xffffffffu, s, o);
    float mu = s * (1.0f / DD);
    float dx0 = v.x - mu, dx1 = v.y - mu, dx2 = v.z - mu, dx3 = v.w - mu;
    float sq = dx0*dx0 + dx1*dx1 + dx2*dx2 + dx3*dx3;
    #pragma unroll
    for (int o = 16; o; o >>= 1) sq += __shfl_xor_sync(0xffffffffu, sq, o);
    float rstd = rsqrtf(sq * (1.0f / DD) + LN_EPS);
    float4 wv = ((const float4*)w)[lane];
    float4 bv = ((const float4*)b)[lane];
    float4 out;
    out.x = tfr(dx0 * rstd * wv.x + bv.x);
    out.y = tfr(dx1 * rstd * wv.y + bv.y);
    out.z = tfr(dx2 * rstd * wv.z + bv.z);
    out.w = tfr(dx3 * rstd * wv.w + bv.w);
    ((float4*)(g_xnorm + (size_t)token * DD))[lane] = out;
}

// ================= K1: QKV GEMM tf32 (16384 x 768 x 128), 2-stage cp.async =================
#define QKV_SAT (128*36)
#define QKV_SBT (32*136)
__global__ __launch_bounds__(256) void qkv_gemm(const float* __restrict__ wq,
                                                const float* __restrict__ wk,
                                                const float* __restrict__ wv){
    extern __shared__ float dynsm[];
    float* sA = dynsm;
    float* sB = dynsm + 2*QKV_SAT;

    int brow = blockIdx.x, bc = blockIdx.y;
    int tid = threadIdx.x;
    int w = tid >> 5, lane = tid & 31, g = lane >> 2, q = lane & 3;
    int wm = w >> 2, wn = w & 3;
    const float* W = (bc < 2) ? wq : (bc < 4 ? wk : wv);
    int colbase = (bc & 1) * 128;
    float4 acc[4][4];
    #pragma unroll
    for (int i = 0; i < 4; i++)
        #pragma unroll
        for (int j = 0; j < 4; j++) acc[i][j] = make_float4(0.f,0.f,0.f,0.f);

    #pragma unroll
    for (int f = tid; f < 1024; f += 256){
        int r = f >> 3, c4 = f & 7;
        cp16(sA + r*36 + c4*4, g_xnorm + (size_t)(brow*128 + r)*DD + c4*4);
    }
    #pragma unroll
    for (int f = tid; f < 1024; f += 256){
        int kr = f >> 5, c4 = f & 31;
        cp16(sB + kr*136 + c4*4, W + (size_t)kr*256 + colbase + c4*4);
    }
    CP_COMMIT;

    for (int kc = 0; kc < 4; kc++){
        if (kc + 1 < 4){
            float* dA = sA + ((kc+1)&1)*QKV_SAT;
            float* dB = sB + ((kc+1)&1)*QKV_SBT;
            #pragma unroll
            for (int f = tid; f < 1024; f += 256){
                int r = f >> 3, c4 = f & 7;
                cp16(dA + r*36 + c4*4, g_xnorm + (size_t)(brow*128 + r)*DD + (kc+1)*32 + c4*4);
            }
            #pragma unroll
            for (int f = tid; f < 1024; f += 256){
                int kr = f >> 5, c4 = f & 31;
                cp16(dB + kr*136 + c4*4, W + (size_t)((kc+1)*32 + kr)*256 + colbase + c4*4);
            }
            CP_COMMIT;
            CP_WAIT1;
        } else {
            CP_WAIT0;
        }
        __syncthreads();
        const float* sAc = sA + (kc&1)*QKV_SAT;
        const float* sBc = sB + (kc&1)*QKV_SBT;
        #pragma unroll
        for (int ks = 0; ks < 4; ks++){
            uint32_t a[4][4];
            int kk = ks*8 + q;
            #pragma unroll
            for (int mt = 0; mt < 4; mt++){
                int r = wm*64 + mt*16 + g;
                a[mt][0] = __float_as_uint(sAc[r*36 + kk]);
                a[mt][1] = __float_as_uint(sAc[(r+8)*36 + kk]);
                a[mt][2] = __float_as_uint(sAc[r*36 + kk + 4]);
                a[mt][3] = __float_as_uint(sAc[(r+8)*36 + kk + 4]);
            }
            #pragma unroll
            for (int nt = 0; nt < 4; nt++){
                uint32_t b[2];
                int n = wn*32 + nt*8 + g;
                b[0] = __float_as_uint(sBc[kk*136 + n]);
                b[1] = __float_as_uint(sBc[(kk+4)*136 + n]);
                #pragma unroll
                for (int mt = 0; mt < 4; mt++)
                    mma8(acc[mt][nt], a[mt], b, acc[mt][nt]);
            }
        }
        __syncthreads();
    }

    int mat = bc >> 1;
    float* dst = (mat == 0) ? g_Q : (mat == 1 ? g_K : g_V);
    #pragma unroll
    for (int mt = 0; mt < 4; mt++){
        int r0 = brow*128 + wm*64 + mt*16 + g;
        int r1 = r0 + 8;
        int b0_ = r0 >> 11, t0 = r0 & (TT-1);
        int b1_ = r1 >> 11, t1 = r1 & (TT-1);
        #pragma unroll
        for (int nt = 0; nt < 4; nt++){
            int col = colbase + wn*32 + nt*8 + 2*q;
            int head = col >> 6, dim = col & 63;
            float* p0 = dst + ((size_t)((b0_*HH + head)*TT + t0))*DH + dim;
            float* p1 = dst + ((size_t)((b1_*HH + head)*TT + t1))*DH + dim;
            *(float2*)p0 = make_float2(tfr(acc[mt][nt].x), tfr(acc[mt][nt].y));
            *(float2*)p1 = make_float2(tfr(acc[mt][nt].z), tfr(acc[mt][nt].w));
        }
    }
}

// ================= K2: branch-parallel banded dual-softmax attention =================
// 256 threads, 8 warps: warp = (branch bw in {0,1}) x (q-strip wq in 0..3).
// No online max (scores deterministically bounded); l reduced once at end.
#define SKT (64*68)
#define SVT (64*72)
#define SPW (16*36)
__global__ __launch_bounds__(256) void attn_kernel(
        const float* __restrict__ lq1, const float* __restrict__ lk1,
        const float* __restrict__ lq2, const float* __restrict__ lk2,
        const float* __restrict__ sig_s_p, const float* __restrict__ sig_n_p,
        const float* __restrict__ hnw, const float* __restrict__ hnb){
    extern __shared__ float dynsm[];
    float* sQ = dynsm;              // [64][68]
    float* sK = dynsm + 64*68;      // 2 stages [64 keys][68]
    float* sV = sK + 2*SKT;         // 2 stages [64 keys][72]
    float* sPb = sV + 2*SVT;        // 8 warps x [16][36]; reused as combine buf [64][72]

    int bh = blockIdx.y;
    int q0 = blockIdx.x * 64;
    int tid = threadIdx.x;
    int w = tid >> 5, lane = tid & 31, g = lane >> 2, q = lane & 3;
    int bw = w & 1, wq = w >> 1;
    float* sP = sPb + w*SPW;

    const float* Qb = g_Q + (size_t)bh * TT * DH;
    const float* Kb = g_K + (size_t)bh * TT * DH;
    const float* Vb = g_V + (size_t)bh * TT * DH;

    int klo = q0 - BAND; if (klo < 0) klo = 0;
    int khi = q0 + 64 + BAND; if (khi > TT) khi = TT;
    int ntile = (khi - klo) >> 6;

    #pragma unroll
    for (int f = tid; f < 1024; f += 256){
        int r = f >> 4, c4 = f & 15;
        cp16(sQ + r*68 + c4*4, Qb + (size_t)(q0 + r)*DH + c4*4);
    }
    CP_COMMIT;
    #pragma unroll
    for (int f = tid; f < 1024; f += 256){
        int kk = f >> 4, c4 = f & 15;
        cp16(sK + kk*68 + c4*4, Kb + (size_t)(klo + kk)*DH + c4*4);
        cp16(sV + kk*72 + c4*4, Vb + (size_t)(klo + kk)*DH + c4*4);
    }
    CP_COMMIT;

    float e1 = 0.f, e2 = 0.f;
    #pragma unroll
    for (int i = 0; i < HD; i++){ e1 += lq1[i]*lk1[i]; e2 += lq2[i]*lk2[i]; }
    float lam = __expf(e1) - __expf(e2) + LAMBDA_INIT;
    float sig_s = fmaxf(sig_s_p[0], 1.0f), sig_n = fmaxf(sig_n_p[0], 1.0f);
    float sc2 = SCALE * LOG2E;
    float cb = bw ? (-0.5f * LOG2E / (sig_n * sig_n))
                  : (-0.5f * LOG2E / (sig_s * sig_s));

    CP_WAIT1;
    __syncthreads();

    // preload Q a-frags for this warp's branch + strip
    uint32_t qa[4][4];
    {
        int rb = (wq*16 + g)*68 + bw*32;
        #pragma unroll
        for (int ks = 0; ks < 4; ks++){
            int d0 = ks*8 + q;
            qa[ks][0] = __float_as_uint(sQ[rb + d0]);
            qa[ks][1] = __float_as_uint(sQ[rb + 8*68 + d0]);
            qa[ks][2] = __float_as_uint(sQ[rb + d0 + 4]);
            qa[ks][3] = __float_as_uint(sQ[rb + 8*68 + d0 + 4]);
        }
    }

    float4 o[8];
    #pragma unroll
    for (int nt = 0; nt < 8; nt++) o[nt] = make_float4(0.f,0.f,0.f,0.f);
    float l_lo = 0.f, l_hi = 0.f;

    float row_lo = (float)(q0 + wq*16 + g);
    float row_hi = row_lo + 8.0f;

    for (int it = 0; it < ntile; it++){
        int ksb = klo + it*64;
        if (it + 1 < ntile){
            float* dK = sK + ((it+1)&1)*SKT;
            float* dV = sV + ((it+1)&1)*SVT;
            int kn = klo + (it+1)*64;
            #pragma unroll
            for (int f = tid; f < 1024; f += 256){
                int kk = f >> 4, c4 = f & 15;
                cp16(dK + kk*68 + c4*4, Kb + (size_t)(kn + kk)*DH + c4*4);
                cp16(dV + kk*72 + c4*4, Vb + (size_t)(kn + kk)*DH + c4*4);
            }
            CP_COMMIT;
            CP_WAIT1;
        } else {
            CP_WAIT0;
        }
        __syncthreads();
        const float* sKc = sK + (it&1)*SKT;
        const float* sVc = sV + (it&1)*SVT;

        // ---- scores over 64 keys (this warp's branch only) ----
        float4 s[8];
        #pragma unroll
        for (int nt = 0; nt < 8; nt++) s[nt] = make_float4(0.f,0.f,0.f,0.f);
        #pragma unroll
        for (int ks = 0; ks < 4; ks++){
            int d0 = ks*8 + q + bw*32;
            #pragma unroll
            for (int nt = 0; nt < 8; nt++){
                uint32_t b[2];
                int kb = (nt*8 + g)*68 + d0;
                b[0] = __float_as_uint(sKc[kb]);
                b[1] = __float_as_uint(sKc[kb + 4]);
                mma8(s[nt], qa[ks], b, s[nt]);
            }
        }

        // ---- bias + exp (fixed reference), two 32-key halves for P/PV ----
        #pragma unroll
        for (int half = 0; half < 2; half++){
            #pragma unroll
            for (int nth = 0; nth < 4; nth++){
                int nt = half*4 + nth;
                float k0f = (float)(ksb + nt*8 + 2*q);
                float rx_lo = k0f - row_lo,  ry_lo = k0f + 1.0f - row_lo;
                float rx_hi = k0f - row_hi,  ry_hi = k0f + 1.0f - row_hi;
                float ax = exp2f(s[nt].x*sc2 + rx_lo*rx_lo*cb);
                float ay = exp2f(s[nt].y*sc2 + ry_lo*ry_lo*cb);
                float az = exp2f(s[nt].z*sc2 + rx_hi*rx_hi*cb);
                float aw = exp2f(s[nt].w*sc2 + ry_hi*ry_hi*cb);
                l_lo += ax + ay;  l_hi += az + aw;
                *(float2*)(sP + g*36 + nth*8 + 2*q)     = make_float2(ax, ay);
                *(float2*)(sP + (g+8)*36 + nth*8 + 2*q) = make_float2(az, aw);
            }
            __syncwarp();
            #pragma unroll
            for (int ks = 0; ks < 4; ks++){
                uint32_t a[4];
                int pk = ks*8 + q;
                a[0] = __float_as_uint(sP[g*36 + pk]);
                a[1] = __float_as_uint(sP[(g+8)*36 + pk]);
                a[2] = __float_as_uint(sP[g*36 + pk + 4]);
                a[3] = __float_as_uint(sP[(g+8)*36 + pk + 4]);
                int kv = half*32 + ks*8 + q;
                #pragma unroll
                for (int nt = 0; nt < 8; nt++){
                    uint32_t b[2];
                    b[0] = __float_as_uint(sVc[kv*72 + nt*8 + g]);
                    b[1] = __float_as_uint(sVc[(kv+4)*72 + nt*8 + g]);
                    mma8(o[nt], a, b, o[nt]);
                }
            }
            __syncwarp();
        }
        __syncthreads();   // K/V stage consumed; also fences sPb reuse below
    }

    // ---- reduce l over quad ----
    #pragma unroll
    for (int os = 1; os <= 2; os <<= 1){
        l_lo += __shfl_xor_sync(0xffffffffu, l_lo, os);
        l_hi += __shfl_xor_sync(0xffffffffu, l_hi, os);
    }

    // ---- branch combine via smem (sPb reused as [64][72] float buffer) ----
    if (bw == 1){
        float s_lo = lam / l_lo, s_hi = lam / l_hi;
        int rb0 = (wq*16 + g)*72, rb1 = (wq*16 + g + 8)*72;
        #pragma unroll
        for (int nt = 0; nt < 8; nt++){
            *(float2*)(sPb + rb0 + nt*8 + 2*q) = make_float2(o[nt].x*s_lo, o[nt].y*s_lo);
            *(float2*)(sPb + rb1 + nt*8 + 2*q) = make_float2(o[nt].z*s_hi, o[nt].w*s_hi);
        }
    }
    __syncthreads();
    if (bw == 0){
        float i_lo = 1.0f / l_lo, i_hi = 1.0f / l_hi;
        int rb0 = (wq*16 + g)*72, rb1 = (wq*16 + g + 8)*72;
        float4 ov[8];
        float slo = 0.f, shi = 0.f;
        #pragma unroll
        for (int nt = 0; nt < 8; nt++){
            float2 c0 = *(const float2*)(sPb + rb0 + nt*8 + 2*q);
            float2 c1 = *(const float2*)(sPb + rb1 + nt*8 + 2*q);
            ov[nt].x = o[nt].x*i_lo - c0.x;
            ov[nt].y = o[nt].y*i_lo - c0.y;
            ov[nt].z = o[nt].z*i_hi - c1.x;
            ov[nt].w = o[nt].w*i_hi - c1.y;
            slo += ov[nt].x + ov[nt].y;
            shi += ov[nt].z + ov[nt].w;
        }
        #pragma unroll
        for (int os = 1; os <= 2; os <<= 1){
            slo += __shfl_xor_sync(0xffffffffu, slo, os);
            shi += __shfl_xor_sync(0xffffffffu, shi, os);
        }
        float mulo = slo * (1.0f / DH), muhi = shi * (1.0f / DH);
        float vlo = 0.f, vhi = 0.f;
        #pragma unroll
        for (int nt = 0; nt < 8; nt++){
            float a0 = ov[nt].x - mulo, a1 = ov[nt].y - mulo;
            float a2 = ov[nt].z - muhi, a3 = ov[nt].w - muhi;
            vlo += a0*a0 + a1*a1;  vhi += a2*a2 + a3*a3;
        }
        #pragma unroll
        for (int os = 1; os <= 2; os <<= 1){
            vlo += __shfl_xor_sync(0xffffffffu, vlo, os);
            vhi += __shfl_xor_sync(0xffffffffu, vhi, os);
        }
        float rslo = rsqrtf(vlo * (1.0f / DH) + LN_EPS);
        float rshi = rsqrtf(vhi * (1.0f / DH) + LN_EPS);

        int b_ = bh >> 2, h = bh & 3;
        int tok_lo = b_*TT + q0 + wq*16 + g;
        float* OdLo = g_O + (size_t)tok_lo*256 + h*DH;
        float* OdHi = OdLo + 8*256;
        #pragma unroll
        for (int nt = 0; nt < 8; nt++){
            float2 wv2 = *(const float2*)(hnw + nt*8 + 2*q);
            float2 bv2 = *(const float2*)(hnb + nt*8 + 2*q);
            float y0 = ((ov[nt].x - mulo)*rslo*wv2.x + bv2.x) * (1.0f - LAMBDA_INIT);
            float y1 = ((ov[nt].y - mulo)*rslo*wv2.y + bv2.y) * (1.0f - LAMBDA_INIT);
            float y2 = ((ov[nt].z - muhi)*rshi*wv2.x + bv2.x) * (1.0f - LAMBDA_INIT);
            float y3 = ((ov[nt].w - muhi)*rshi*wv2.y + bv2.y) * (1.0f - LAMBDA_INIT);
            *(float2*)(OdLo + nt*8 + 2*q) = make_float2(y0, y1);
            *(float2*)(OdHi + nt*8 + 2*q) = make_float2(y2, y3);
        }
    }
}

// ================= K3: output GEMM tf32 (16384 x 128 x 256) + residual =================
#define OUT_SAT (64*36)
#define OUT_SBT (32*136)
__global__ __launch_bounds__(256) void out_gemm(const float* __restrict__ wo,
                                                const float* __restrict__ tokens,
                                                float* __restrict__ out){
    extern __shared__ float dynsm[];
    float* sA = dynsm;                 // 2 stages [64][36]
    float* sB = dynsm + 2*OUT_SAT;     // 2 stages [32][136]

    int brow = blockIdx.x;             // 0..255
    int tid = threadIdx.x;
    int w = tid >> 5, lane = tid & 31, g = lane >> 2, q = lane & 3;
    int wm = w >> 2, wn = w & 3;
    float4 acc[2][4];
    #pragma unroll
    for (int i = 0; i < 2; i++)
        #pragma unroll
        for (int j = 0; j < 4; j++) acc[i][j] = make_float4(0.f,0.f,0.f,0.f);

    #pragma unroll
    for (int f = tid; f < 512; f += 256){
        int r = f >> 3, c4 = f & 7;
        cp16(sA + r*36 + c4*4, g_O + (size_t)(brow*64 + r)*256 + c4*4);
    }
    #pragma unroll
    for (int f = tid; f < 1024; f += 256){
        int kr = f >> 5, c4 = f & 31;
        cp16(sB + kr*136 + c4*4, wo + (size_t)kr*DD + c4*4);
    }
    CP_COMMIT;

    for (int kc = 0; kc < 8; kc++){
        if (kc + 1 < 8){
            float* dA = sA + ((kc+1)&1)*OUT_SAT;
            float* dB = sB + ((kc+1)&1)*OUT_SBT;
            #pragma unroll
            for (int f = tid; f < 512; f += 256){
                int r = f >> 3, c4 = f & 7;
                cp16(dA + r*36 + c4*4, g_O + (size_t)(brow*64 + r)*256 + (kc+1)*32 + c4*4);
            }
            #pragma unroll
            for (int f = tid; f < 1024; f += 256){
                int kr = f >> 5, c4 = f & 31;
                cp16(dB + kr*136 + c4*4, wo + (size_t)((kc+1)*32 + kr)*DD + c4*4);
            }
            CP_COMMIT;
            CP_WAIT1;
        } else {
            CP_WAIT0;
        }
        __syncthreads();
        const float* sAc = sA + (kc&1)*OUT_SAT;
        const float* sBc = sB + (kc&1)*OUT_SBT;
        #pragma unroll
        for (int ks = 0; ks < 4; ks++){
            uint32_t a[2][4];
            int kk = ks*8 + q;
            #pragma unroll
            for (int mt = 0; mt < 2; mt++){
                int r = wm*32 + mt*16 + g;
                a[mt][0] = __float_as_uint(sAc[r*36 + kk]);
                a[mt][1] = __float_as_uint(sAc[(r+8)*36 + kk]);
                a[mt][2] = __float_as_uint(sAc[r*36 + kk + 4]);
                a[mt][3] = __float_as_uint(sAc[(r+8)*36 + kk + 4]);
            }
            #pragma unroll
            for (int nt = 0; nt < 4; nt++){
                uint32_t b[2];
                int n = wn*32 + nt*8 + g;
                b[0] = __float_as_uint(sBc[kk*136 + n]);
                b[1] = __float_as_uint(sBc[(kk+4)*136 + n]);
                #pragma unroll
                for (int mt = 0; mt < 2; mt++)
                    mma8(acc[mt][nt], a[mt], b, acc[mt][nt]);
            }
        }
        __syncthreads();
    }

    #pragma unroll
    for (int mt = 0; mt < 2; mt++){
        int r0 = brow*64 + wm*32 + mt*16 + g;
        int r1 = r0 + 8;
        #pragma unroll
        for (int nt = 0; nt < 4; nt++){
            int col = wn*32 + nt*8 + 2*q;
            float2 t0 = *(const float2*)(tokens + (size_t)r0*DD + col);
            float2 t1 = *(const float2*)(tokens + (size_t)r1*DD + col);
            *(float2*)(out + (size_t)r0*DD + col) = make_float2(acc[mt][nt].x + t0.x, acc[mt][nt].y + t0.y);
            *(float2*)(out + (size_t)r1*DD + col) = make_float2(acc[mt][nt].z + t1.x, acc[mt][nt].w + t1.y);
        }
    }
}

// ================= launch =================
#define QKV_SMEM ((2*QKV_SAT + 2*QKV_SBT) * 4)
#define ATTN_SMEM ((64*68 + 2*SKT + 2*SVT + 8*SPW) * 4)
#define OUT_SMEM ((2*OUT_SAT + 2*OUT_SBT) * 4)

extern "C" void kernel_launch(void* const* d_in, const int* in_sizes, int n_in,
                              void* d_out, int out_size){
    const float* tokens = (const float*)d_in[0];
    const float* ln_w   = (const float*)d_in[1];
    const float* ln_b   = (const float*)d_in[2];
    const float* wq     = (const float*)d_in[3];
    const float* wk     = (const float*)d_in[4];
    const float* wv     = (const float*)d_in[5];
    const float* wo     = (const float*)d_in[6];
    const float* lq1    = (const float*)d_in[7];
    const float* lk1    = (const float*)d_in[8];
    const float* lq2    = (const float*)d_in[9];
    const float* lk2    = (const float*)d_in[10];
    const float* sig_s  = (const float*)d_in[11];
    const float* sig_n  = (const float*)d_in[12];
    const float* hnw    = (const float*)d_in[13];
    const float* hnb    = (const float*)d_in[14];
    float* out = (float*)d_out;

    static int attr_done = 0;
    if (!attr_done){
        cudaFuncSetAttribute(qkv_gemm, cudaFuncAttributeMaxDynamicSharedMemorySize, QKV_SMEM);
        cudaFuncSetAttribute(attn_kernel, cudaFuncAttributeMaxDynamicSharedMemorySize, ATTN_SMEM);
        cudaFuncSetAttribute(out_gemm, cudaFuncAttributeMaxDynamicSharedMemorySize, OUT_SMEM);
        attr_done = 1;
    }

    ln_kernel<<<NTOK/8, dim3(32,8)>>>(tokens, ln_w, ln_b);
    qkv_gemm<<<dim3(NTOK/128, 6), 256, QKV_SMEM>>>(wq, wk, wv);
    attn_kernel<<<dim3(TT/64, BB*HH), 256, ATTN_SMEM>>>(lq1, lk1, lq2, lk2, sig_s, sig_n, hnw, hnb);
    out_gemm<<<NTOK/64, 256, OUT_SMEM>>>(wo, tokens, out);
}